// round 3
// baseline (speedup 1.0000x reference)
#include <cuda_runtime.h>
#include <cstdint>

typedef unsigned long long ull;

#define WS      8
#define SHIFT   4
#define DSTATE  8
#define DCONV   4
#define DINNER  256
#define DTRANK  16
#define LTOK    64
#define NWIN    1024
#define LDT     66              // token stride (floats) in [channel][token] buffers
#define NTHR    512

// -------- transposed weight scratch (device globals; no allocation) --------
__device__ float g_WinT[256 * 512];   // [d][e]
__device__ float g_WoutT[256 * 256];  // [d][e]
__device__ float g_WxT[256 * 32];     // [d][e]
__device__ float g_WdtT[16 * 256];    // [r][d]

__global__ void prep_transpose_kernel(const float* __restrict__ W_in,
                                      const float* __restrict__ W_xproj,
                                      const float* __restrict__ W_dt,
                                      const float* __restrict__ W_out) {
    int idx = blockIdx.x * blockDim.x + threadIdx.x;
    int stride = gridDim.x * blockDim.x;
    for (int i = idx; i < 512 * 256; i += stride) {
        int e = i / 256, d = i % 256;
        g_WinT[d * 512 + e] = W_in[i];
    }
    for (int i = idx; i < 256 * 256; i += stride) {
        int e = i / 256, d = i % 256;
        g_WoutT[d * 256 + e] = W_out[i];
    }
    for (int i = idx; i < 32 * 256; i += stride) {
        int e = i / 256, d = i % 256;
        g_WxT[d * 32 + e] = W_xproj[i];
    }
    for (int i = idx; i < 256 * 16; i += stride) {
        int d = i / 16, r = i % 16;
        g_WdtT[r * 256 + d] = W_dt[i];
    }
}

__device__ __forceinline__ void fma2(ull& d, ull a, ull b) {
    asm("fma.rn.f32x2 %0, %1, %2, %0;" : "+l"(d) : "l"(a), "l"(b));
}
__device__ __forceinline__ float silu_f(float v) {
    return v / (1.0f + __expf(-v));
}

// out[e][t] (64 tokens x 256 e-cols) = sIn[k][t] (256 x 64, transposed) @ Wt[k][ecol0+e]
// 512 threads: tx = e-group (stride 32), ty = t-block of 4 rows.
// Weights staged duplicated (w,w) in sW2[8][512] so B operand is a direct LDS.64.
__device__ void gemm_T(const float* __restrict__ Wt, int ldw, int ecol0,
                       const float* sIn, float* sOut, float* sW2, int tid) {
    const int tx = tid & 31;
    const int ty = tid >> 5;       // 0..15
    const int tb = ty * 4;
    const int c = tid & 255;
    const int half4 = (tid >> 8) * 4;  // 0 or 4

    ull acc[2][8];
#pragma unroll
    for (int p = 0; p < 2; p++)
#pragma unroll
        for (int jj = 0; jj < 8; jj++) acc[p][jj] = 0ull;

    float pre[4];
#pragma unroll
    for (int i = 0; i < 4; i++)
        pre[i] = Wt[(half4 + i) * ldw + ecol0 + c];

    for (int k0 = 0; k0 < 256; k0 += 8) {
        __syncthreads();  // previous chunk readers done with sW2
#pragma unroll
        for (int i = 0; i < 4; i++) {
            float2 v = make_float2(pre[i], pre[i]);
            *(float2*)&sW2[(half4 + i) * 512 + 2 * c] = v;
        }
        __syncthreads();
        if (k0 + 8 < 256) {
#pragma unroll
            for (int i = 0; i < 4; i++)
                pre[i] = Wt[(k0 + 8 + half4 + i) * ldw + ecol0 + c];
        }
#pragma unroll
        for (int j = 0; j < 8; j++) {
            ull a0 = *(const ull*)&sIn[(k0 + j) * LDT + tb];      // (t, t+1) pair, bcast
            ull a1 = *(const ull*)&sIn[(k0 + j) * LDT + tb + 2];  // (t+2, t+3) pair
#pragma unroll
            for (int jj = 0; jj < 8; jj++) {
                ull b = *(const ull*)&sW2[j * 512 + 2 * (tx + 32 * jj)];
                fma2(acc[0][jj], a0, b);
                fma2(acc[1][jj], a1, b);
            }
        }
    }
#pragma unroll
    for (int jj = 0; jj < 8; jj++) {
        int e = tx + 32 * jj;
        *(ull*)&sOut[e * LDT + tb] = acc[0][jj];
        *(ull*)&sOut[e * LDT + tb + 2] = acc[1][jj];
    }
}

// smem: sA | sB | sC (each 256*LDT) | sW2 (8*512, aliased by sBC 64*32)
#define SMEM_FLOATS (3 * 256 * LDT + 8 * 512)
#define SMEM_BYTES (SMEM_FLOATS * 4)

__global__ __launch_bounds__(NTHR, 1) void swin_mamba_kernel(
    const float* __restrict__ x, const float* __restrict__ ln_g,
    const float* __restrict__ ln_b, const float* __restrict__ conv_w,
    const float* __restrict__ conv_b, const float* __restrict__ b_dt,
    const float* __restrict__ A_log, const float* __restrict__ D_param,
    float* __restrict__ out) {
    extern __shared__ float smem[];
    float* sA = smem;                 // xn -> xs/y  [c][t]
    float* sB = sA + 256 * LDT;       // raw x -> xc -> dt  [c][t]
    float* sC = sB + 256 * LDT;       // z -> out tile  [c][t]
    float* sW2 = sC + 256 * LDT;      // weight staging [8][512]
    float* sBC = sW2;                 // x_dbl [64][32] (aliased; disjoint lifetimes)

    const int tid = threadIdx.x;
    const int n = blockIdx.x;
    const int b = n >> 8;
    const int rem = n & 255;
    const int wy = rem >> 4;
    const int wx = rem & 15;

    // ---- phase 0: gather rolled window into sB [c][t] ----
#pragma unroll 4
    for (int i = 0; i < 32; i++) {
        int idx = tid + NTHR * i;
        int ix = idx & 7;
        int c = (idx >> 3) & 255;
        int iy = idx >> 11;
        int t = iy * 8 + ix;
        int h = (wy * 8 + iy + SHIFT) & 127;
        int w = (wx * 8 + ix + SHIFT) & 127;
        sB[c * LDT + t] = x[(((b * 256 + c) << 7) + h) * 128 + w];
    }
    __syncthreads();

    // ---- phase 1: LayerNorm over c, sB -> sA [c][t] ----
    {
        const int wid = tid >> 5, lane = tid & 31;
#pragma unroll
        for (int t = wid; t < 64; t += 16) {
            float v[8], s = 0.f, s2 = 0.f;
#pragma unroll
            for (int j = 0; j < 8; j++) {
                v[j] = sB[(lane + 32 * j) * LDT + t];
                s += v[j];
                s2 += v[j] * v[j];
            }
#pragma unroll
            for (int o = 16; o > 0; o >>= 1) {
                s += __shfl_xor_sync(0xffffffffu, s, o);
                s2 += __shfl_xor_sync(0xffffffffu, s2, o);
            }
            float mu = s * (1.0f / 256.0f);
            float var = s2 * (1.0f / 256.0f) - mu * mu;
            float rstd = rsqrtf(var + 1e-5f);
#pragma unroll
            for (int j = 0; j < 8; j++) {
                int c = lane + 32 * j;
                sA[c * LDT + t] = (v[j] - mu) * rstd * ln_g[c] + ln_b[c];
            }
        }
    }
    __syncthreads();

    // ---- phase 2: xz = xn @ W_in^T : xc -> sB, z -> sC ----
    gemm_T(g_WinT, 512, 0, sA, sB, sW2, tid);
    __syncthreads();
    gemm_T(g_WinT, 512, 256, sA, sC, sW2, tid);
    __syncthreads();

    // ---- phase 3: depthwise causal conv + SiLU: sB -> sA ----
    {
        const int d = tid & 255;
        const int hf = tid >> 8;
        const int t0 = hf * 32;
        float w0 = conv_w[d * 4 + 0], w1 = conv_w[d * 4 + 1];
        float w2 = conv_w[d * 4 + 2], w3 = conv_w[d * 4 + 3];
        float cb = conv_b[d];
        float q0, q1, q2;
        if (hf == 0) { q0 = q1 = q2 = 0.f; }
        else {
            q0 = sB[d * LDT + 29];
            q1 = sB[d * LDT + 30];
            q2 = sB[d * LDT + 31];
        }
#pragma unroll 4
        for (int t = t0; t < t0 + 32; t++) {
            float q3 = sB[d * LDT + t];
            float v = cb + w0 * q0 + w1 * q1 + w2 * q2 + w3 * q3;
            sA[d * LDT + t] = silu_f(v);
            q0 = q1; q1 = q2; q2 = q3;
        }
    }
    __syncthreads();

    // ---- phase 4: x_dbl = xs @ W_xproj^T -> sBC [64][32] ----
    {
        const int e = tid & 31;
        const int tq = (tid >> 5) * 4;
        float a4[4] = {0.f, 0.f, 0.f, 0.f};
#pragma unroll 4
        for (int k = 0; k < 256; k++) {
            float wv = g_WxT[k * 32 + e];
            float x0 = sA[k * LDT + tq + 0];
            float x1 = sA[k * LDT + tq + 1];
            float x2 = sA[k * LDT + tq + 2];
            float x3 = sA[k * LDT + tq + 3];
            a4[0] = fmaf(x0, wv, a4[0]);
            a4[1] = fmaf(x1, wv, a4[1]);
            a4[2] = fmaf(x2, wv, a4[2]);
            a4[3] = fmaf(x3, wv, a4[3]);
        }
        __syncthreads();  // sW2 (aliased) no longer read by anyone
#pragma unroll
        for (int i = 0; i < 4; i++) sBC[(tq + i) * 32 + e] = a4[i];
    }
    __syncthreads();

    // ---- phase 5: dt_full = softplus(dt_raw @ W_dt^T + b_dt) -> sB [e][t] ----
    {
        const int tx = tid & 31;
        const int tb = (tid >> 5) * 4;
        float acc5[4][8];
#pragma unroll
        for (int i = 0; i < 4; i++)
#pragma unroll
            for (int jj = 0; jj < 8; jj++) acc5[i][jj] = 0.f;
#pragma unroll
        for (int r = 0; r < 16; r++) {
            float wv[8];
#pragma unroll
            for (int jj = 0; jj < 8; jj++) wv[jj] = g_WdtT[r * 256 + tx + 32 * jj];
#pragma unroll
            for (int i = 0; i < 4; i++) {
                float dv = sBC[(tb + i) * 32 + r];
#pragma unroll
                for (int jj = 0; jj < 8; jj++)
                    acc5[i][jj] = fmaf(dv, wv[jj], acc5[i][jj]);
            }
        }
#pragma unroll
        for (int jj = 0; jj < 8; jj++) {
            int e = tx + 32 * jj;
            float bb = b_dt[e];
#pragma unroll
            for (int i = 0; i < 4; i++) {
                float v = acc5[i][jj] + bb;
                v = (v > 20.0f) ? v : log1pf(__expf(v));
                sB[e * LDT + tb + i] = v;
            }
        }
    }
    __syncthreads();

    // ---- phase 6: selective scan + D skip + z gate: y -> sA [d][t] ----
    if (tid < 256) {
        const int d = tid;
        float Aa[8];
#pragma unroll
        for (int s = 0; s < 8; s++) Aa[s] = -__expf(A_log[d * 8 + s]);
        float Dv = D_param[d];
        float h[8];
#pragma unroll
        for (int s = 0; s < 8; s++) h[s] = 0.f;
#pragma unroll 2
        for (int t = 0; t < 64; t++) {
            float dtv = sB[d * LDT + t];
            float xsv = sA[d * LDT + t];
            float zv = sC[d * LDT + t];
            float dbx = dtv * xsv;
            float y = 0.f;
#pragma unroll
            for (int s = 0; s < 8; s++) {
                float Bv = sBC[t * 32 + 16 + s];
                float Cv = sBC[t * 32 + 24 + s];
                h[s] = __expf(dtv * Aa[s]) * h[s] + dbx * Bv;
                y = fmaf(h[s], Cv, y);
            }
            y = fmaf(Dv, xsv, y);
            sA[d * LDT + t] = y * silu_f(zv);
        }
    }
    __syncthreads();

    // ---- phase 7: out = y @ W_out^T -> sC [e][t] ----
    gemm_T(g_WoutT, 256, 0, sA, sC, sW2, tid);
    __syncthreads();

    // ---- phase 8: window-reverse scatter store ----
#pragma unroll 4
    for (int i = 0; i < 32; i++) {
        int idx = tid + NTHR * i;
        int ix = idx & 7;
        int e = (idx >> 3) & 255;
        int iy = idx >> 11;
        int t = iy * 8 + ix;
        int h = (wy * 8 + iy + SHIFT) & 127;
        int w = (wx * 8 + ix + SHIFT) & 127;
        out[(((b * 256 + e) << 7) + h) * 128 + w] = sC[e * LDT + t];
    }
}

extern "C" void kernel_launch(void* const* d_in, const int* in_sizes, int n_in,
                              void* d_out, int out_size) {
    const float* x = (const float*)d_in[0];
    const float* ln_g = (const float*)d_in[1];
    const float* ln_b = (const float*)d_in[2];
    const float* W_in = (const float*)d_in[3];
    const float* conv_w = (const float*)d_in[4];
    const float* conv_b = (const float*)d_in[5];
    const float* W_xproj = (const float*)d_in[6];
    const float* W_dt = (const float*)d_in[7];
    const float* b_dt = (const float*)d_in[8];
    const float* A_log = (const float*)d_in[9];
    const float* D_param = (const float*)d_in[10];
    const float* W_out = (const float*)d_in[11];
    float* out = (float*)d_out;

    prep_transpose_kernel<<<256, 256>>>(W_in, W_xproj, W_dt, W_out);

    cudaFuncSetAttribute(swin_mamba_kernel,
                         cudaFuncAttributeMaxDynamicSharedMemorySize, SMEM_BYTES);
    swin_mamba_kernel<<<NWIN, NTHR, SMEM_BYTES>>>(x, ln_g, ln_b, conv_w, conv_b,
                                                  b_dt, A_log, D_param, out);
}